// round 12
// baseline (speedup 1.0000x reference)
#include <cuda_runtime.h>
#include <cuda_bf16.h>
#include <cstdint>

#define NTOKEN 33278
#define NINP   400
#define KPAD   448
#define NHID   1150
#define NHP    1152
#define SLEN   70
#define BATCH  128
#define NS     10
#define SB     (SLEN*BATCH)
#define TEMP   65.0f
#define EPSV   1e-6f

// persistent scan config: 18 n-tiles(64) x 8 k-splits(144)
#define NBLK   144
#define SC_KS  8
#define SC_KC  144
#define SC_PAD 152

// ---------------- device scratch ----------------
__device__ __align__(16) __nv_bfloat16 A448[(size_t)NTOKEN * KPAD];
__device__ __align__(16) __nv_bfloat16 Wb448[(size_t)NHP * KPAD];     // W_ih hi
__device__ __align__(16) __nv_bfloat16 WbLo448[(size_t)NHP * KPAD];   // W_ih lo
__device__ __align__(16) __nv_bfloat16 EglH[(size_t)NTOKEN * NHP];
__device__ __align__(16) float scanE[(size_t)SB * NHP];
__device__ __align__(16) float RO[(size_t)(SLEN + 1) * BATCH * NHP];
__device__ __align__(16) __nv_bfloat16 ROh[(size_t)(SLEN + 1) * BATCH * NHP];
__device__ __align__(16) __nv_bfloat16 ROl[(size_t)(SLEN + 1) * BATCH * NHP];
__device__ __align__(16) float HU[(size_t)SLEN * BATCH * NHP];
__device__ __align__(16) float HUP[(size_t)SC_KS * BATCH * NHP];
__device__ double ACCpos, ACClog, ACCbias;
__device__ unsigned GBAR;

// ---------------- misc helpers ----------------
__device__ __forceinline__ float tanh_fast(float x) {
    float r; asm("tanh.approx.f32 %0, %1;" : "=f"(r) : "f"(x)); return r;
}
__device__ __forceinline__ float4 ldcg4(const float* p) {
    float4 v;
    asm volatile("ld.global.cg.v4.f32 {%0,%1,%2,%3}, [%4];"
                 : "=f"(v.x), "=f"(v.y), "=f"(v.z), "=f"(v.w) : "l"(p));
    return v;
}
__device__ __forceinline__ uint32_t smem_u32(const void* p) {
    uint32_t a;
    asm("{ .reg .u64 t; cvta.to.shared.u64 t, %1; cvt.u32.u64 %0, t; }" : "=r"(a) : "l"(p));
    return a;
}
#define SW128(o)   ((o) ^ (((o) >> 3) & 0x70))

// ---------------- HMMA helpers ----------------
__device__ __forceinline__ void ldsm4(uint32_t* r, uint32_t addr) {
    asm volatile("ldmatrix.sync.aligned.m8n8.x4.shared.b16 {%0,%1,%2,%3}, [%4];"
                 : "=r"(r[0]), "=r"(r[1]), "=r"(r[2]), "=r"(r[3]) : "r"(addr));
}
__device__ __forceinline__ void mma16816(float* d, const uint32_t* a, uint32_t b0, uint32_t b1) {
    asm volatile(
        "mma.sync.aligned.m16n8k16.row.col.f32.bf16.bf16.f32 "
        "{%0,%1,%2,%3}, {%4,%5,%6,%7}, {%8,%9}, {%0,%1,%2,%3};"
        : "+f"(d[0]), "+f"(d[1]), "+f"(d[2]), "+f"(d[3])
        : "r"(a[0]), "r"(a[1]), "r"(a[2]), "r"(a[3]), "r"(b0), "r"(b1));
}

// ---------------- grid barrier (release-atomic arrival) ----------------
__device__ __forceinline__ void grid_bar(unsigned target) {
    __syncthreads();
    if (threadIdx.x == 0) {
        asm volatile("red.release.gpu.global.add.u32 [%0], 1;" :: "l"(&GBAR) : "memory");
        unsigned v;
        do {
            asm volatile("ld.acquire.gpu.global.u32 %0, [%1];" : "=r"(v) : "l"(&GBAR) : "memory");
        } while (v < target);
    }
    __syncthreads();
}

// ---------------- init ----------------
__global__ void k_init(const float* __restrict__ hidden) {
    int i = blockIdx.x * blockDim.x + threadIdx.x;
    int stride = gridDim.x * blockDim.x;
    if (i == 0) { ACCpos = 0.0; ACClog = 0.0; ACCbias = 0.0; GBAR = 0u; }
    const int nrow0 = BATCH * NHP;
    for (int idx = i; idx < nrow0; idx += stride) {
        int b = idx / NHP, c = idx % NHP;
        float v = (c < NHID) ? hidden[b * NHID + c] : 0.f;
        RO[idx] = v;
        __nv_bfloat16 hi = __float2bfloat16(v);
        ROh[idx] = hi;
        ROl[idx] = __float2bfloat16(v - __bfloat162float(hi));
    }
}

// ---------------- bf16 conversion / padding (+ W_ih hi/lo split) ----------------
__global__ void k_conv(const float* __restrict__ emb_W, const float* __restrict__ W_ih) {
    size_t i = (size_t)blockIdx.x * blockDim.x + threadIdx.x;
    size_t stride = (size_t)gridDim.x * blockDim.x;
    const size_t na = (size_t)NTOKEN * KPAD;
    const size_t nb = (size_t)NHP * KPAD;
    for (size_t idx = i; idx < na + nb; idx += stride) {
        if (idx < na) {
            size_t k = idx % KPAD;
            size_t m = idx / KPAD;
            A448[idx] = (k < NINP) ? __float2bfloat16(emb_W[m * NINP + k])
                                   : __float2bfloat16(0.f);
        } else {
            size_t j = idx - na;
            size_t k = j % KPAD;
            size_t n = j / KPAD;
            float w = (n < NHID && k < NINP) ? W_ih[n * NINP + k] : 0.f;
            __nv_bfloat16 hi = __float2bfloat16(w);
            Wb448[j] = hi;
            WbLo448[j] = __float2bfloat16(w - __bfloat162float(hi));
        }
    }
}

// ---------------- vocab E GEMM via HMMA (bf16, negpos only) ----------------
__global__ __launch_bounds__(256) void k_egemm_mma(const float* __restrict__ bih) {
    __shared__ __align__(16) uint8_t smA[128 * 128];
    __shared__ __align__(16) uint8_t smB[128 * 128];
    __shared__ float bihs[128];

    const int tid = threadIdx.x, wid = tid >> 5, lane = tid & 31;
    const int bm = blockIdx.y * 128, bn = blockIdx.x * 128;
    const int wm = wid & 1, wn = wid >> 1;

    if (tid < 128) { int n = bn + tid; bihs[tid] = (n < NHID) ? bih[n] : 0.f; }

    const uint32_t sA = smem_u32(smA);
    const uint32_t sB = smem_u32(smB);

    float acc[4][4][4];
    #pragma unroll
    for (int mi = 0; mi < 4; mi++)
        #pragma unroll
        for (int nj = 0; nj < 4; nj++)
            #pragma unroll
            for (int f = 0; f < 4; f++) acc[mi][nj][f] = 0.f;

    const int grp = lane >> 3, lr = lane & 7;

    // chunks 0..5 full (cols 0..384)
    for (int ch = 0; ch < 6; ch++) {
        __syncthreads();
        #pragma unroll
        for (int i = 0; i < 4; i++) {
            int u = tid + i * 256;
            int row = u >> 3, c8 = u & 7;
            int m = bm + row; if (m >= NTOKEN) m = NTOKEN - 1;
            uint32_t swo = SW128((uint32_t)(row * 128 + c8 * 16));
            *(uint4*)(smA + swo) = *(const uint4*)(A448 + (size_t)m * KPAD + ch * 64 + c8 * 8);
            *(uint4*)(smB + swo) = *(const uint4*)(Wb448 + (size_t)(bn + row) * KPAD + ch * 64 + c8 * 8);
        }
        __syncthreads();

        #pragma unroll
        for (int k16 = 0; k16 < 4; k16++) {
            const int k0 = k16 * 16;
            uint32_t bfr[2][4];
            #pragma unroll
            for (int j = 0; j < 2; j++) {
                int row = wn * 32 + j * 16 + (grp & 1) * 8 + lr;
                int col = k0 + (grp >> 1) * 8;
                ldsm4(bfr[j], sB + SW128((uint32_t)(row * 128 + col * 2)));
            }
            #pragma unroll
            for (int mi = 0; mi < 4; mi++) {
                uint32_t afr[4];
                int row = wm * 64 + mi * 16 + (grp & 1) * 8 + lr;
                int col = k0 + (grp >> 1) * 8;
                ldsm4(afr, sA + SW128((uint32_t)(row * 128 + col * 2)));
                #pragma unroll
                for (int nj = 0; nj < 4; nj++) {
                    const uint32_t* bf = bfr[nj >> 1];
                    mma16816(acc[mi][nj], afr, bf[nj & 1], bf[2 + (nj & 1)]);
                }
            }
        }
    }

    // tail: cols 384..400 only (16 k) — zero-padding beyond 400 skipped (bit-identical)
    {
        __syncthreads();
        if (tid < 256) {
            int row = tid >> 1, c8 = tid & 1;
            int m = bm + row; if (m >= NTOKEN) m = NTOKEN - 1;
            uint32_t swo = SW128((uint32_t)(row * 128 + c8 * 16));
            *(uint4*)(smA + swo) = *(const uint4*)(A448 + (size_t)m * KPAD + 384 + c8 * 8);
            *(uint4*)(smB + swo) = *(const uint4*)(Wb448 + (size_t)(bn + row) * KPAD + 384 + c8 * 8);
        }
        __syncthreads();

        uint32_t bfr[2][4];
        #pragma unroll
        for (int j = 0; j < 2; j++) {
            int row = wn * 32 + j * 16 + (grp & 1) * 8 + lr;
            int col = (grp >> 1) * 8;
            ldsm4(bfr[j], sB + SW128((uint32_t)(row * 128 + col * 2)));
        }
        #pragma unroll
        for (int mi = 0; mi < 4; mi++) {
            uint32_t afr[4];
            int row = wm * 64 + mi * 16 + (grp & 1) * 8 + lr;
            int col = (grp >> 1) * 8;
            ldsm4(afr, sA + SW128((uint32_t)(row * 128 + col * 2)));
            #pragma unroll
            for (int nj = 0; nj < 4; nj++) {
                const uint32_t* bf = bfr[nj >> 1];
                mma16816(acc[mi][nj], afr, bf[nj & 1], bf[2 + (nj & 1)]);
            }
        }
    }

    #pragma unroll
    for (int mi = 0; mi < 4; mi++) {
        int row0 = wm * 64 + mi * 16 + (lane >> 2);
        int m0g = bm + row0, m1g = m0g + 8;
        #pragma unroll
        for (int nj = 0; nj < 4; nj++) {
            int cloc = wn * 32 + nj * 8 + (lane & 3) * 2;
            float b0 = bihs[cloc], b1 = bihs[cloc + 1];
            int n = bn + cloc;
            if (m0g < NTOKEN) {
                __nv_bfloat162 p = __floats2bfloat162_rn(acc[mi][nj][0] + b0, acc[mi][nj][1] + b1);
                *(__nv_bfloat162*)(EglH + (size_t)m0g * NHP + n) = p;
            }
            if (m1g < NTOKEN) {
                __nv_bfloat162 p = __floats2bfloat162_rn(acc[mi][nj][2] + b0, acc[mi][nj][3] + b1);
                *(__nv_bfloat162*)(EglH + (size_t)m1g * NHP + n) = p;
            }
        }
    }
}

// ---------------- scanE via split-bf16 HMMA (gathered rows, fp32-grade) ----------------
#define SMEM_SE (4 * 16384 + 512)
__global__ __launch_bounds__(256) void k_scane_mma(const float* __restrict__ A,
                                                   const int* __restrict__ data,
                                                   const float* __restrict__ bih) {
    extern __shared__ char sm[];
    uint8_t* smAh = (uint8_t*)sm;
    uint8_t* smAl = smAh + 16384;
    uint8_t* smBh = smAl + 16384;
    uint8_t* smBl = smBh + 16384;
    float* bihs = (float*)(smBl + 16384);

    const int tid = threadIdx.x, wid = tid >> 5, lane = tid & 31;
    const int bm = blockIdx.y * 128, bn = blockIdx.x * 128;
    const int wm = wid & 1, wn = wid >> 1;
    const int grp = lane >> 3, lr = lane & 7;

    if (tid < 128) { int n = bn + tid; bihs[tid] = (n < NHID) ? bih[n] : 0.f; }

    const uint32_t sAh = smem_u32(smAh), sAl = smem_u32(smAl);
    const uint32_t sBh = smem_u32(smBh), sBl = smem_u32(smBl);

    const int arow = tid >> 1, ahalf = tid & 1;
    const int tok = data[bm + arow];
    const float* Arow = A + (size_t)tok * NINP;

    float acc[4][4][4];
    #pragma unroll
    for (int mi = 0; mi < 4; mi++)
        #pragma unroll
        for (int nj = 0; nj < 4; nj++)
            #pragma unroll
            for (int f = 0; f < 4; f++) acc[mi][nj][f] = 0.f;

    // chunks 0..5 full
    for (int ch = 0; ch < 6; ch++) {
        __syncthreads();
        #pragma unroll
        for (int s = 0; s < 4; s++) {
            int lc = ahalf * 32 + s * 8;
            int gc = ch * 64 + lc;
            __nv_bfloat16 h[8], l[8];
            float4 v0 = *(const float4*)(Arow + gc);
            float4 v1 = *(const float4*)(Arow + gc + 4);
            float vs[8] = {v0.x, v0.y, v0.z, v0.w, v1.x, v1.y, v1.z, v1.w};
            #pragma unroll
            for (int e = 0; e < 8; e++) {
                h[e] = __float2bfloat16(vs[e]);
                l[e] = __float2bfloat16(vs[e] - __bfloat162float(h[e]));
            }
            uint32_t swo = SW128((uint32_t)(arow * 128 + lc * 2));
            *(uint4*)(smAh + swo) = *(uint4*)&h[0];
            *(uint4*)(smAl + swo) = *(uint4*)&l[0];
        }
        #pragma unroll
        for (int i = 0; i < 4; i++) {
            int u = tid + i * 256;
            int row = u >> 3, c8 = u & 7;
            uint32_t swo = SW128((uint32_t)(row * 128 + c8 * 16));
            size_t go = (size_t)(bn + row) * KPAD + ch * 64 + c8 * 8;
            *(uint4*)(smBh + swo) = *(const uint4*)(Wb448 + go);
            *(uint4*)(smBl + swo) = *(const uint4*)(WbLo448 + go);
        }
        __syncthreads();

        #pragma unroll
        for (int k16 = 0; k16 < 4; k16++) {
            const int col = k16 * 16 + (grp >> 1) * 8;
            uint32_t bh[2][4], bl[2][4];
            #pragma unroll
            for (int j = 0; j < 2; j++) {
                int row = wn * 32 + j * 16 + (grp & 1) * 8 + lr;
                uint32_t off = SW128((uint32_t)(row * 128 + col * 2));
                ldsm4(bh[j], sBh + off);
                ldsm4(bl[j], sBl + off);
            }
            #pragma unroll
            for (int mi = 0; mi < 4; mi++) {
                int row = wm * 64 + mi * 16 + (grp & 1) * 8 + lr;
                uint32_t off = SW128((uint32_t)(row * 128 + col * 2));
                uint32_t ah[4], al[4];
                ldsm4(ah, sAh + off);
                ldsm4(al, sAl + off);
                #pragma unroll
                for (int nj = 0; nj < 4; nj++) {
                    const uint32_t* bfh = bh[nj >> 1];
                    const uint32_t* bfl = bl[nj >> 1];
                    mma16816(acc[mi][nj], ah, bfh[nj & 1], bfh[2 + (nj & 1)]);
                    mma16816(acc[mi][nj], ah, bfl[nj & 1], bfl[2 + (nj & 1)]);
                    mma16816(acc[mi][nj], al, bfh[nj & 1], bfh[2 + (nj & 1)]);
                }
            }
        }
    }

    // tail: cols 384..400 only (16 k)
    {
        __syncthreads();
        {
            // A: rows 0..127, elements 384..400 (lc 0..16), 256 threads x 8 elems
            int lc = ahalf * 8;           // 0 or 8
            int gc = 384 + lc;
            __nv_bfloat16 h[8], l[8];
            float4 v0 = *(const float4*)(Arow + gc);
            float4 v1 = *(const float4*)(Arow + gc + 4);
            float vs[8] = {v0.x, v0.y, v0.z, v0.w, v1.x, v1.y, v1.z, v1.w};
            #pragma unroll
            for (int e = 0; e < 8; e++) {
                h[e] = __float2bfloat16(vs[e]);
                l[e] = __float2bfloat16(vs[e] - __bfloat162float(h[e]));
            }
            uint32_t swo = SW128((uint32_t)(arow * 128 + lc * 2));
            *(uint4*)(smAh + swo) = *(uint4*)&h[0];
            *(uint4*)(smAl + swo) = *(uint4*)&l[0];
            // B: rows 0..127, c8 0..1
            int row = tid >> 1, c8 = tid & 1;
            uint32_t swb = SW128((uint32_t)(row * 128 + c8 * 16));
            size_t go = (size_t)(bn + row) * KPAD + 384 + c8 * 8;
            *(uint4*)(smBh + swb) = *(const uint4*)(Wb448 + go);
            *(uint4*)(smBl + swb) = *(const uint4*)(WbLo448 + go);
        }
        __syncthreads();

        const int col = (grp >> 1) * 8;
        uint32_t bh[2][4], bl[2][4];
        #pragma unroll
        for (int j = 0; j < 2; j++) {
            int row = wn * 32 + j * 16 + (grp & 1) * 8 + lr;
            uint32_t off = SW128((uint32_t)(row * 128 + col * 2));
            ldsm4(bh[j], sBh + off);
            ldsm4(bl[j], sBl + off);
        }
        #pragma unroll
        for (int mi = 0; mi < 4; mi++) {
            int row = wm * 64 + mi * 16 + (grp & 1) * 8 + lr;
            uint32_t off = SW128((uint32_t)(row * 128 + col * 2));
            uint32_t ah[4], al[4];
            ldsm4(ah, sAh + off);
            ldsm4(al, sAl + off);
            #pragma unroll
            for (int nj = 0; nj < 4; nj++) {
                const uint32_t* bfh = bh[nj >> 1];
                const uint32_t* bfl = bl[nj >> 1];
                mma16816(acc[mi][nj], ah, bfh[nj & 1], bfh[2 + (nj & 1)]);
                mma16816(acc[mi][nj], ah, bfl[nj & 1], bfl[2 + (nj & 1)]);
                mma16816(acc[mi][nj], al, bfh[nj & 1], bfh[2 + (nj & 1)]);
            }
        }
    }

    #pragma unroll
    for (int mi = 0; mi < 4; mi++) {
        int row0 = wm * 64 + mi * 16 + (lane >> 2);
        int j0 = bm + row0, j1 = j0 + 8;
        #pragma unroll
        for (int nj = 0; nj < 4; nj++) {
            int cloc = wn * 32 + nj * 8 + (lane & 3) * 2;
            float b0 = bihs[cloc], b1 = bihs[cloc + 1];
            int n = bn + cloc;
            *(float2*)(scanE + (size_t)j0 * NHP + n) =
                make_float2(acc[mi][nj][0] + b0, acc[mi][nj][1] + b1);
            *(float2*)(scanE + (size_t)j1 * NHP + n) =
                make_float2(acc[mi][nj][2] + b0, acc[mi][nj][3] + b1);
        }
    }
}

// ---------------- persistent scan: bf16-split HMMA, W fragments in registers ----------------
#define SMEM_SCAN (2 * 128 * SC_PAD * 2 + 2 * 64 * SC_PAD * 2)

__global__ __launch_bounds__(512) void k_scan(const float* __restrict__ W_hh,
                                              const float* __restrict__ b_hh) {
    extern __shared__ char smc[];
    __nv_bfloat16* Ahi = (__nv_bfloat16*)smc;
    __nv_bfloat16* Alo = Ahi + 128 * SC_PAD;
    __nv_bfloat16* Whi = Alo + 128 * SC_PAD;
    __nv_bfloat16* Wlo = Whi + 64 * SC_PAD;
    const uint32_t sAhi = smem_u32(Ahi), sAlo = smem_u32(Alo);
    const uint32_t sWhi = smem_u32(Whi), sWlo = smem_u32(Wlo);

    const int tid = threadIdx.x, wid = tid >> 5, lane = tid & 31;
    const int bn = blockIdx.x / SC_KS;
    const int kz = blockIdx.x % SC_KS;
    const int kbase = kz * SC_KC;
    const int wm = wid & 3, wn = wid >> 2;
    const int grp = lane >> 3, lr = lane & 7;

    for (int idx = tid; idx < 64 * SC_KC; idx += 512) {
        int n = idx / SC_KC, k = idx % SC_KC;
        int gn = bn * 64 + n, gk = kbase + k;
        float w = (gn < NHID && gk < NHID) ? W_hh[(size_t)gn * NHID + gk] : 0.f;
        __nv_bfloat16 hi = __float2bfloat16(w);
        float lo = w - __bfloat162float(hi);
        Whi[n * SC_PAD + k] = hi;
        Wlo[n * SC_PAD + k] = __float2bfloat16(lo);
    }
    __syncthreads();

    // hoist loop-invariant W fragments into registers (once for all 70 steps)
    uint32_t wbh[9][4], wbl[9][4];
    {
        const int brow = wn * 16 + (grp & 1) * 8 + lr;
        #pragma unroll
        for (int k16 = 0; k16 < 9; k16++) {
            const int col = k16 * 16 + (grp >> 1) * 8;
            ldsm4(wbh[k16], sWhi + (uint32_t)(brow * (SC_PAD * 2) + col * 2));
            ldsm4(wbl[k16], sWlo + (uint32_t)(brow * (SC_PAD * 2) + col * 2));
        }
    }

    unsigned barid = 0;

    for (int t = 0; t < SLEN; t++) {
        // stage A: straight copy of pre-split ROh/ROl
        {
            const __nv_bfloat16* Sh = ROh + (size_t)t * BATCH * NHP + kbase;
            const __nv_bfloat16* Sl = ROl + (size_t)t * BATCH * NHP + kbase;
            #pragma unroll
            for (int it = 0; it < 5; it++) {
                int idx = tid + it * 512;
                if (idx < 2304) {                 // 128 rows x 18 uint4-chunks
                    int row = idx / 18, ch = idx % 18;
                    size_t gso = (size_t)row * NHP + ch * 8;
                    int dso = row * SC_PAD + ch * 8;
                    *(uint4*)(Ahi + dso) = *(const uint4*)(Sh + gso);
                    *(uint4*)(Alo + dso) = *(const uint4*)(Sl + gso);
                }
            }
        }
        __syncthreads();

        float acc[2][2][4];
        #pragma unroll
        for (int mi = 0; mi < 2; mi++)
            #pragma unroll
            for (int nj = 0; nj < 2; nj++)
                #pragma unroll
                for (int f = 0; f < 4; f++) acc[mi][nj][f] = 0.f;

        #pragma unroll
        for (int k16 = 0; k16 < 9; k16++) {
            const int col = k16 * 16 + (grp >> 1) * 8;
            #pragma unroll
            for (int mi = 0; mi < 2; mi++) {
                const int arow = wm * 32 + mi * 16 + (grp & 1) * 8 + lr;
                uint32_t ah[4], al[4];
                ldsm4(ah, sAhi + (uint32_t)(arow * (SC_PAD * 2) + col * 2));
                ldsm4(al, sAlo + (uint32_t)(arow * (SC_PAD * 2) + col * 2));
                #pragma unroll
                for (int nj = 0; nj < 2; nj++) {
                    mma16816(acc[mi][nj], ah, wbh[k16][nj], wbh[k16][2 + nj]);
                    mma16816(acc[mi][nj], ah, wbl[k16][nj], wbl[k16][2 + nj]);
                    mma16816(acc[mi][nj], al, wbh[k16][nj], wbh[k16][2 + nj]);
                }
            }
        }

        {
            float* P = HUP + (size_t)kz * BATCH * NHP + bn * 64;
            #pragma unroll
            for (int mi = 0; mi < 2; mi++) {
                int r0 = wm * 32 + mi * 16 + (lane >> 2);
                #pragma unroll
                for (int nj = 0; nj < 2; nj++) {
                    int c0 = wn * 16 + nj * 8 + (lane & 3) * 2;
                    *(float2*)(P + (size_t)r0 * NHP + c0) =
                        make_float2(acc[mi][nj][0], acc[mi][nj][1]);
                    *(float2*)(P + (size_t)(r0 + 8) * NHP + c0) =
                        make_float2(acc[mi][nj][2], acc[mi][nj][3]);
                }
            }
        }

        barid++; grid_bar(barid * NBLK);

        // combine (vectorized) + single-site hi/lo split for next step's staging
        if (tid < 256) {
            const int i = blockIdx.x * 1024 + tid * 4;
            const float* Et = scanE + (size_t)t * BATCH * NHP;
            float4 hu4 = ldcg4(HUP + i);
            #pragma unroll
            for (int z = 1; z < SC_KS; z++) {
                float4 v = ldcg4(HUP + (size_t)z * BATCH * NHP + i);
                hu4.x += v.x; hu4.y += v.y; hu4.z += v.z; hu4.w += v.w;
            }
            float4 et = *(const float4*)(Et + i);
            int ccol = i % NHP;
            float hv[4] = {hu4.x, hu4.y, hu4.z, hu4.w};
            float ev[4] = {et.x, et.y, et.z, et.w};
            float ro4[4], hu4o[4];
            __nv_bfloat16 h4[4], l4[4];
            #pragma unroll
            for (int e = 0; e < 4; e++) {
                int c = ccol + e;
                if (c < NHID) {
                    float hu = hv[e] + b_hh[c];
                    ro4[e] = tanh_fast(ev[e] + hu);
                    hu4o[e] = hu;
                } else {
                    ro4[e] = 0.f; hu4o[e] = 0.f;
                }
                h4[e] = __float2bfloat16(ro4[e]);
                l4[e] = __float2bfloat16(ro4[e] - __bfloat162float(h4[e]));
            }
            size_t o1 = (size_t)(t + 1) * BATCH * NHP + i;
            *(float4*)(RO + o1) = make_float4(ro4[0], ro4[1], ro4[2], ro4[3]);
            *(uint2*)(ROh + o1) = *(uint2*)&h4[0];
            *(uint2*)(ROl + o1) = *(uint2*)&l4[0];
            *(float4*)(HU + (size_t)t * BATCH * NHP + i) =
                make_float4(hu4o[0], hu4o[1], hu4o[2], hu4o[3]);
        }

        if (t + 1 < SLEN) { barid++; grid_bar(barid * NBLK); }
    }
}

// ---------------- fused negatives + positives ----------------
__global__ __launch_bounds__(128) void k_negpos(const int* __restrict__ samples,
                                                const int* __restrict__ data,
                                                const float* __restrict__ bias) {
    int j = blockIdx.x;
    __shared__ float fl[NHID], hus[NHID];
    __shared__ float red[4];
    const float* flat = RO + (size_t)j * NHP;
    const float* nxt  = RO + (size_t)(j + BATCH) * NHP;
    const float* huj  = HU + (size_t)j * NHP;
    int tid = threadIdx.x;

    float pp = 0.f;
    for (int c = tid; c < NHID; c += 128) {
        float f = flat[c];
        float d = f - nxt[c];
        pp += d * d;
        fl[c] = f; hus[c] = huj[c];
    }
    #pragma unroll
    for (int o = 16; o > 0; o >>= 1) pp += __shfl_down_sync(0xffffffffu, pp, o);
    if ((tid & 31) == 0) red[tid >> 5] = pp;
    __syncthreads();
    float possum = red[0] + red[1] + red[2] + red[3];
    __syncthreads();

    float s = 0.f;
    for (int n = 0; n < NS; n++) {
        int tok = samples[n * SB + j];
        const __nv_bfloat16* er = EglH + (size_t)tok * NHP;
        float part = 0.f;
        for (int c = tid; c < NHID; c += 128) {
            float v = tanh_fast(__bfloat162float(er[c]) + hus[c]);
            float d = fl[c] - v;
            part += d * d;
        }
        #pragma unroll
        for (int o = 16; o > 0; o >>= 1) part += __shfl_down_sync(0xffffffffu, part, o);
        if ((tid & 31) == 0) red[tid >> 5] = part;
        __syncthreads();
        if (tid == 0) {
            float dist = red[0] + red[1] + red[2] + red[3] - bias[tok];
            s += __expf(-TEMP * dist);
        }
        __syncthreads();
    }
    if (tid == 0) {
        float pos = TEMP * (possum - bias[data[j]]);
        float se = __expf(-pos) + s;
        atomicAdd(&ACCpos, (double)pos);
        atomicAdd(&ACClog, (double)logf(se + EPSV));
    }
}

__global__ void k_bias2(const float* __restrict__ bias) {
    __shared__ float sh[256];
    int i = blockIdx.x * blockDim.x + threadIdx.x;
    float v = 0.f;
    if (i < NTOKEN) { float b = bias[i]; v = b * b; }
    sh[threadIdx.x] = v;
    __syncthreads();
    for (int o = 128; o > 0; o >>= 1) {
        if (threadIdx.x < o) sh[threadIdx.x] += sh[threadIdx.x + o];
        __syncthreads();
    }
    if (threadIdx.x == 0) atomicAdd(&ACCbias, (double)sh[0]);
}

// fused: loss scalar + new_hidden copy in one launch
__global__ void k_out(float* out, int out_size) {
    int i = blockIdx.x * blockDim.x + threadIdx.x;
    if (i == 0 && out_size >= 1) {
        double loss = ACCpos / (double)SB + ACClog / (double)SB + ACCbias;
        out[0] = (float)loss;
    }
    if (i < BATCH * NHID && 1 + i < out_size) {
        int b = i / NHID, c = i % NHID;
        out[1 + i] = RO[(size_t)(SLEN * BATCH + b) * NHP + c];
    }
}

// ---------------- launch ----------------
extern "C" void kernel_launch(void* const* d_in, const int* in_sizes, int n_in,
                              void* d_out, int out_size) {
    const int*   data    = (const int*)d_in[0];
    const float* hidden  = (const float*)d_in[1];
    const int*   samples = (const int*)d_in[2];
    const float* emb_W   = (const float*)d_in[3];
    const float* W_ih    = (const float*)d_in[4];
    const float* b_ih    = (const float*)d_in[5];
    const float* W_hh    = (const float*)d_in[6];
    const float* b_hh    = (const float*)d_in[7];
    const float* bias    = (const float*)d_in[8];
    float* out = (float*)d_out;
    (void)in_sizes; (void)n_in;

    cudaFuncSetAttribute(k_scan, cudaFuncAttributeMaxDynamicSharedMemorySize, SMEM_SCAN);
    cudaFuncSetAttribute(k_scane_mma, cudaFuncAttributeMaxDynamicSharedMemorySize, SMEM_SE);

    k_init<<<256, 256>>>(hidden);
    k_conv<<<8192, 256>>>(emb_W, W_ih);

    dim3 ge(9, 260);
    k_egemm_mma<<<ge, 256>>>(b_ih);

    dim3 gs(9, 70);
    k_scane_mma<<<gs, 256, SMEM_SE>>>(emb_W, data, b_ih);

    k_scan<<<NBLK, 512, SMEM_SCAN>>>(W_hh, b_hh);

    k_negpos<<<SB, 128>>>(samples, data, bias);
    k_bias2<<<(NTOKEN + 255) / 256, 256>>>(bias);
    const int nb = (BATCH * NHID + 255) / 256;
    k_out<<<nb, 256>>>(out, out_size);
}

// round 13
// speedup vs baseline: 1.0327x; 1.0327x over previous
#include <cuda_runtime.h>
#include <cuda_bf16.h>
#include <cstdint>

#define NTOKEN 33278
#define NINP   400
#define KPAD   448
#define NHID   1150
#define NHP    1152
#define SLEN   70
#define BATCH  128
#define NS     10
#define SB     (SLEN*BATCH)
#define TEMP   65.0f
#define EPSV   1e-6f

// persistent scan config: 18 n-tiles(64) x 8 k-splits(144)
#define NBLK   144
#define SC_KS  8
#define SC_KC  144
#define SC_PAD 152

// ---------------- device scratch ----------------
__device__ __align__(16) __nv_bfloat16 A448[(size_t)NTOKEN * KPAD];
__device__ __align__(16) __nv_bfloat16 Wb448[(size_t)NHP * KPAD];     // W_ih hi
__device__ __align__(16) __nv_bfloat16 WbLo448[(size_t)NHP * KPAD];   // W_ih lo
__device__ __align__(16) __nv_bfloat16 EglH[(size_t)NTOKEN * NHP];
__device__ __align__(16) float scanE[(size_t)SB * NHP];
__device__ __align__(16) float RO[(size_t)(SLEN + 1) * BATCH * NHP];
__device__ __align__(16) __nv_bfloat16 ROh[(size_t)(SLEN + 1) * BATCH * NHP];
__device__ __align__(16) __nv_bfloat16 ROl[(size_t)(SLEN + 1) * BATCH * NHP];
__device__ __align__(16) float HU[(size_t)SLEN * BATCH * NHP];
__device__ __align__(16) float HUP[(size_t)SC_KS * BATCH * NHP];
__device__ double ACCpos, ACClog, ACCbias;
__device__ unsigned GBAR;

// ---------------- misc helpers ----------------
__device__ __forceinline__ float tanh_fast(float x) {
    float r; asm("tanh.approx.f32 %0, %1;" : "=f"(r) : "f"(x)); return r;
}
__device__ __forceinline__ float4 ldcg4(const float* p) {
    float4 v;
    asm volatile("ld.global.cg.v4.f32 {%0,%1,%2,%3}, [%4];"
                 : "=f"(v.x), "=f"(v.y), "=f"(v.z), "=f"(v.w) : "l"(p));
    return v;
}
__device__ __forceinline__ uint32_t smem_u32(const void* p) {
    uint32_t a;
    asm("{ .reg .u64 t; cvta.to.shared.u64 t, %1; cvt.u32.u64 %0, t; }" : "=r"(a) : "l"(p));
    return a;
}
#define SW128(o)   ((o) ^ (((o) >> 3) & 0x70))

// ---------------- HMMA helpers ----------------
__device__ __forceinline__ void ldsm4(uint32_t* r, uint32_t addr) {
    asm volatile("ldmatrix.sync.aligned.m8n8.x4.shared.b16 {%0,%1,%2,%3}, [%4];"
                 : "=r"(r[0]), "=r"(r[1]), "=r"(r[2]), "=r"(r[3]) : "r"(addr));
}
__device__ __forceinline__ void mma16816(float* d, const uint32_t* a, uint32_t b0, uint32_t b1) {
    asm volatile(
        "mma.sync.aligned.m16n8k16.row.col.f32.bf16.bf16.f32 "
        "{%0,%1,%2,%3}, {%4,%5,%6,%7}, {%8,%9}, {%0,%1,%2,%3};"
        : "+f"(d[0]), "+f"(d[1]), "+f"(d[2]), "+f"(d[3])
        : "r"(a[0]), "r"(a[1]), "r"(a[2]), "r"(a[3]), "r"(b0), "r"(b1));
}

// ---------------- grid barrier (R11-proven form) ----------------
__device__ __forceinline__ void grid_bar(unsigned target) {
    __syncthreads();
    if (threadIdx.x == 0) {
        __threadfence();
        atomicAdd(&GBAR, 1u);
        unsigned v;
        do {
            asm volatile("ld.acquire.gpu.global.u32 %0, [%1];" : "=r"(v) : "l"(&GBAR) : "memory");
        } while (v < target);
    }
    __syncthreads();
}

// ---------------- init ----------------
__global__ void k_init(const float* __restrict__ hidden) {
    int i = blockIdx.x * blockDim.x + threadIdx.x;
    int stride = gridDim.x * blockDim.x;
    if (i == 0) { ACCpos = 0.0; ACClog = 0.0; ACCbias = 0.0; GBAR = 0u; }
    const int nrow0 = BATCH * NHP;
    for (int idx = i; idx < nrow0; idx += stride) {
        int b = idx / NHP, c = idx % NHP;
        float v = (c < NHID) ? hidden[b * NHID + c] : 0.f;
        RO[idx] = v;
        __nv_bfloat16 hi = __float2bfloat16(v);
        ROh[idx] = hi;
        ROl[idx] = __float2bfloat16(v - __bfloat162float(hi));
    }
}

// ---------------- bf16 conversion / padding, vectorized (bit-identical values) ----------------
// chunks of 8 elements: NINP=400=50*8, KPAD=448=56*8 -> chunks 0..49 valid, 50..55 zero.
__global__ void k_conv(const float* __restrict__ emb_W, const float* __restrict__ W_ih) {
    size_t i = (size_t)blockIdx.x * blockDim.x + threadIdx.x;
    size_t stride = (size_t)gridDim.x * blockDim.x;
    const size_t nca = (size_t)NTOKEN * 56;     // A chunks
    const size_t ncb = (size_t)NHP * 56;        // W chunks
    for (size_t idx = i; idx < nca + ncb; idx += stride) {
        if (idx < nca) {
            size_t m = idx / 56;
            int ch = (int)(idx % 56);
            __nv_bfloat16 h[8];
            if (ch < 50) {
                const float* src = emb_W + m * NINP + ch * 8;
                float4 v0 = *(const float4*)src;
                float4 v1 = *(const float4*)(src + 4);
                float vs[8] = {v0.x, v0.y, v0.z, v0.w, v1.x, v1.y, v1.z, v1.w};
                #pragma unroll
                for (int e = 0; e < 8; e++) h[e] = __float2bfloat16(vs[e]);
            } else {
                #pragma unroll
                for (int e = 0; e < 8; e++) h[e] = __float2bfloat16(0.f);
            }
            *(uint4*)(A448 + m * KPAD + ch * 8) = *(uint4*)&h[0];
        } else {
            size_t j = idx - nca;
            size_t n = j / 56;
            int ch = (int)(j % 56);
            __nv_bfloat16 h[8], l[8];
            if (ch < 50 && n < NHID) {
                const float* src = W_ih + n * NINP + ch * 8;
                float4 v0 = *(const float4*)src;
                float4 v1 = *(const float4*)(src + 4);
                float vs[8] = {v0.x, v0.y, v0.z, v0.w, v1.x, v1.y, v1.z, v1.w};
                #pragma unroll
                for (int e = 0; e < 8; e++) {
                    h[e] = __float2bfloat16(vs[e]);
                    l[e] = __float2bfloat16(vs[e] - __bfloat162float(h[e]));
                }
            } else {
                #pragma unroll
                for (int e = 0; e < 8; e++) { h[e] = __float2bfloat16(0.f); l[e] = h[e]; }
            }
            *(uint4*)(Wb448 + n * KPAD + ch * 8) = *(uint4*)&h[0];
            *(uint4*)(WbLo448 + n * KPAD + ch * 8) = *(uint4*)&l[0];
        }
    }
}

// ---------------- vocab E GEMM via HMMA (bf16, negpos only) ----------------
__global__ __launch_bounds__(256) void k_egemm_mma(const float* __restrict__ bih) {
    __shared__ __align__(16) uint8_t smA[128 * 128];
    __shared__ __align__(16) uint8_t smB[128 * 128];
    __shared__ float bihs[128];

    const int tid = threadIdx.x, wid = tid >> 5, lane = tid & 31;
    const int bm = blockIdx.y * 128, bn = blockIdx.x * 128;
    const int wm = wid & 1, wn = wid >> 1;

    if (tid < 128) { int n = bn + tid; bihs[tid] = (n < NHID) ? bih[n] : 0.f; }

    const uint32_t sA = smem_u32(smA);
    const uint32_t sB = smem_u32(smB);

    float acc[4][4][4];
    #pragma unroll
    for (int mi = 0; mi < 4; mi++)
        #pragma unroll
        for (int nj = 0; nj < 4; nj++)
            #pragma unroll
            for (int f = 0; f < 4; f++) acc[mi][nj][f] = 0.f;

    const int grp = lane >> 3, lr = lane & 7;

    for (int ch = 0; ch < 7; ch++) {
        __syncthreads();
        #pragma unroll
        for (int i = 0; i < 4; i++) {
            int u = tid + i * 256;
            int row = u >> 3, c8 = u & 7;
            int m = bm + row; if (m >= NTOKEN) m = NTOKEN - 1;
            uint32_t swo = SW128((uint32_t)(row * 128 + c8 * 16));
            *(uint4*)(smA + swo) = *(const uint4*)(A448 + (size_t)m * KPAD + ch * 64 + c8 * 8);
            *(uint4*)(smB + swo) = *(const uint4*)(Wb448 + (size_t)(bn + row) * KPAD + ch * 64 + c8 * 8);
        }
        __syncthreads();

        #pragma unroll
        for (int k16 = 0; k16 < 4; k16++) {
            const int k0 = k16 * 16;
            uint32_t bfr[2][4];
            #pragma unroll
            for (int j = 0; j < 2; j++) {
                int row = wn * 32 + j * 16 + (grp & 1) * 8 + lr;
                int col = k0 + (grp >> 1) * 8;
                ldsm4(bfr[j], sB + SW128((uint32_t)(row * 128 + col * 2)));
            }
            #pragma unroll
            for (int mi = 0; mi < 4; mi++) {
                uint32_t afr[4];
                int row = wm * 64 + mi * 16 + (grp & 1) * 8 + lr;
                int col = k0 + (grp >> 1) * 8;
                ldsm4(afr, sA + SW128((uint32_t)(row * 128 + col * 2)));
                #pragma unroll
                for (int nj = 0; nj < 4; nj++) {
                    const uint32_t* bf = bfr[nj >> 1];
                    mma16816(acc[mi][nj], afr, bf[nj & 1], bf[2 + (nj & 1)]);
                }
            }
        }
    }

    #pragma unroll
    for (int mi = 0; mi < 4; mi++) {
        int row0 = wm * 64 + mi * 16 + (lane >> 2);
        int m0g = bm + row0, m1g = m0g + 8;
        #pragma unroll
        for (int nj = 0; nj < 4; nj++) {
            int cloc = wn * 32 + nj * 8 + (lane & 3) * 2;
            float b0 = bihs[cloc], b1 = bihs[cloc + 1];
            int n = bn + cloc;
            if (m0g < NTOKEN) {
                __nv_bfloat162 p = __floats2bfloat162_rn(acc[mi][nj][0] + b0, acc[mi][nj][1] + b1);
                *(__nv_bfloat162*)(EglH + (size_t)m0g * NHP + n) = p;
            }
            if (m1g < NTOKEN) {
                __nv_bfloat162 p = __floats2bfloat162_rn(acc[mi][nj][2] + b0, acc[mi][nj][3] + b1);
                *(__nv_bfloat162*)(EglH + (size_t)m1g * NHP + n) = p;
            }
        }
    }
}

// ---------------- scanE via split-bf16 HMMA (gathered rows, fp32-grade) ----------------
#define SMEM_SE (4 * 16384 + 512)
__global__ __launch_bounds__(256) void k_scane_mma(const float* __restrict__ A,
                                                   const int* __restrict__ data,
                                                   const float* __restrict__ bih) {
    extern __shared__ char sm[];
    uint8_t* smAh = (uint8_t*)sm;
    uint8_t* smAl = smAh + 16384;
    uint8_t* smBh = smAl + 16384;
    uint8_t* smBl = smBh + 16384;
    float* bihs = (float*)(smBl + 16384);

    const int tid = threadIdx.x, wid = tid >> 5, lane = tid & 31;
    const int bm = blockIdx.y * 128, bn = blockIdx.x * 128;
    const int wm = wid & 1, wn = wid >> 1;
    const int grp = lane >> 3, lr = lane & 7;

    if (tid < 128) { int n = bn + tid; bihs[tid] = (n < NHID) ? bih[n] : 0.f; }

    const uint32_t sAh = smem_u32(smAh), sAl = smem_u32(smAl);
    const uint32_t sBh = smem_u32(smBh), sBl = smem_u32(smBl);

    const int arow = tid >> 1, ahalf = tid & 1;
    const int tok = data[bm + arow];
    const float* Arow = A + (size_t)tok * NINP;

    float acc[4][4][4];
    #pragma unroll
    for (int mi = 0; mi < 4; mi++)
        #pragma unroll
        for (int nj = 0; nj < 4; nj++)
            #pragma unroll
            for (int f = 0; f < 4; f++) acc[mi][nj][f] = 0.f;

    for (int ch = 0; ch < 7; ch++) {
        __syncthreads();
        #pragma unroll
        for (int s = 0; s < 4; s++) {
            int lc = ahalf * 32 + s * 8;
            int gc = ch * 64 + lc;
            __nv_bfloat16 h[8], l[8];
            if (gc + 8 <= NINP) {
                float4 v0 = *(const float4*)(Arow + gc);
                float4 v1 = *(const float4*)(Arow + gc + 4);
                float vs[8] = {v0.x, v0.y, v0.z, v0.w, v1.x, v1.y, v1.z, v1.w};
                #pragma unroll
                for (int e = 0; e < 8; e++) {
                    h[e] = __float2bfloat16(vs[e]);
                    l[e] = __float2bfloat16(vs[e] - __bfloat162float(h[e]));
                }
            } else {
                #pragma unroll
                for (int e = 0; e < 8; e++) { h[e] = __float2bfloat16(0.f); l[e] = h[e]; }
            }
            uint32_t swo = SW128((uint32_t)(arow * 128 + lc * 2));
            *(uint4*)(smAh + swo) = *(uint4*)&h[0];
            *(uint4*)(smAl + swo) = *(uint4*)&l[0];
        }
        #pragma unroll
        for (int i = 0; i < 4; i++) {
            int u = tid + i * 256;
            int row = u >> 3, c8 = u & 7;
            uint32_t swo = SW128((uint32_t)(row * 128 + c8 * 16));
            size_t go = (size_t)(bn + row) * KPAD + ch * 64 + c8 * 8;
            *(uint4*)(smBh + swo) = *(const uint4*)(Wb448 + go);
            *(uint4*)(smBl + swo) = *(const uint4*)(WbLo448 + go);
        }
        __syncthreads();

        #pragma unroll
        for (int k16 = 0; k16 < 4; k16++) {
            const int col = k16 * 16 + (grp >> 1) * 8;
            uint32_t bh[2][4], bl[2][4];
            #pragma unroll
            for (int j = 0; j < 2; j++) {
                int row = wn * 32 + j * 16 + (grp & 1) * 8 + lr;
                uint32_t off = SW128((uint32_t)(row * 128 + col * 2));
                ldsm4(bh[j], sBh + off);
                ldsm4(bl[j], sBl + off);
            }
            #pragma unroll
            for (int mi = 0; mi < 4; mi++) {
                int row = wm * 64 + mi * 16 + (grp & 1) * 8 + lr;
                uint32_t off = SW128((uint32_t)(row * 128 + col * 2));
                uint32_t ah[4], al[4];
                ldsm4(ah, sAh + off);
                ldsm4(al, sAl + off);
                #pragma unroll
                for (int nj = 0; nj < 4; nj++) {
                    const uint32_t* bfh = bh[nj >> 1];
                    const uint32_t* bfl = bl[nj >> 1];
                    mma16816(acc[mi][nj], ah, bfh[nj & 1], bfh[2 + (nj & 1)]);
                    mma16816(acc[mi][nj], ah, bfl[nj & 1], bfl[2 + (nj & 1)]);
                    mma16816(acc[mi][nj], al, bfh[nj & 1], bfh[2 + (nj & 1)]);
                }
            }
        }
    }

    #pragma unroll
    for (int mi = 0; mi < 4; mi++) {
        int row0 = wm * 64 + mi * 16 + (lane >> 2);
        int j0 = bm + row0, j1 = j0 + 8;
        #pragma unroll
        for (int nj = 0; nj < 4; nj++) {
            int cloc = wn * 32 + nj * 8 + (lane & 3) * 2;
            float b0 = bihs[cloc], b1 = bihs[cloc + 1];
            int n = bn + cloc;
            *(float2*)(scanE + (size_t)j0 * NHP + n) =
                make_float2(acc[mi][nj][0] + b0, acc[mi][nj][1] + b1);
            *(float2*)(scanE + (size_t)j1 * NHP + n) =
                make_float2(acc[mi][nj][2] + b0, acc[mi][nj][3] + b1);
        }
    }
}

// ---------------- persistent scan: bf16-split HMMA, W fragments in registers ----------------
#define SMEM_SCAN (2 * 128 * SC_PAD * 2 + 2 * 64 * SC_PAD * 2)

__global__ __launch_bounds__(512) void k_scan(const float* __restrict__ W_hh,
                                              const float* __restrict__ b_hh) {
    extern __shared__ char smc[];
    __nv_bfloat16* Ahi = (__nv_bfloat16*)smc;
    __nv_bfloat16* Alo = Ahi + 128 * SC_PAD;
    __nv_bfloat16* Whi = Alo + 128 * SC_PAD;
    __nv_bfloat16* Wlo = Whi + 64 * SC_PAD;
    const uint32_t sAhi = smem_u32(Ahi), sAlo = smem_u32(Alo);
    const uint32_t sWhi = smem_u32(Whi), sWlo = smem_u32(Wlo);

    const int tid = threadIdx.x, wid = tid >> 5, lane = tid & 31;
    const int bn = blockIdx.x / SC_KS;
    const int kz = blockIdx.x % SC_KS;
    const int kbase = kz * SC_KC;
    const int wm = wid & 3, wn = wid >> 2;
    const int grp = lane >> 3, lr = lane & 7;

    for (int idx = tid; idx < 64 * SC_KC; idx += 512) {
        int n = idx / SC_KC, k = idx % SC_KC;
        int gn = bn * 64 + n, gk = kbase + k;
        float w = (gn < NHID && gk < NHID) ? W_hh[(size_t)gn * NHID + gk] : 0.f;
        __nv_bfloat16 hi = __float2bfloat16(w);
        float lo = w - __bfloat162float(hi);
        Whi[n * SC_PAD + k] = hi;
        Wlo[n * SC_PAD + k] = __float2bfloat16(lo);
    }
    __syncthreads();

    // hoist loop-invariant W fragments into registers (once for all 70 steps)
    uint32_t wbh[9][4], wbl[9][4];
    {
        const int brow = wn * 16 + (grp & 1) * 8 + lr;
        #pragma unroll
        for (int k16 = 0; k16 < 9; k16++) {
            const int col = k16 * 16 + (grp >> 1) * 8;
            ldsm4(wbh[k16], sWhi + (uint32_t)(brow * (SC_PAD * 2) + col * 2));
            ldsm4(wbl[k16], sWlo + (uint32_t)(brow * (SC_PAD * 2) + col * 2));
        }
    }

    unsigned barid = 0;

    for (int t = 0; t < SLEN; t++) {
        // stage A: straight copy of pre-split ROh/ROl
        {
            const __nv_bfloat16* Sh = ROh + (size_t)t * BATCH * NHP + kbase;
            const __nv_bfloat16* Sl = ROl + (size_t)t * BATCH * NHP + kbase;
            #pragma unroll
            for (int it = 0; it < 5; it++) {
                int idx = tid + it * 512;
                if (idx < 2304) {                 // 128 rows x 18 uint4-chunks
                    int row = idx / 18, ch = idx % 18;
                    size_t gso = (size_t)row * NHP + ch * 8;
                    int dso = row * SC_PAD + ch * 8;
                    *(uint4*)(Ahi + dso) = *(const uint4*)(Sh + gso);
                    *(uint4*)(Alo + dso) = *(const uint4*)(Sl + gso);
                }
            }
        }
        __syncthreads();

        float acc[2][2][4];
        #pragma unroll
        for (int mi = 0; mi < 2; mi++)
            #pragma unroll
            for (int nj = 0; nj < 2; nj++)
                #pragma unroll
                for (int f = 0; f < 4; f++) acc[mi][nj][f] = 0.f;

        #pragma unroll
        for (int k16 = 0; k16 < 9; k16++) {
            const int col = k16 * 16 + (grp >> 1) * 8;
            #pragma unroll
            for (int mi = 0; mi < 2; mi++) {
                const int arow = wm * 32 + mi * 16 + (grp & 1) * 8 + lr;
                uint32_t ah[4], al[4];
                ldsm4(ah, sAhi + (uint32_t)(arow * (SC_PAD * 2) + col * 2));
                ldsm4(al, sAlo + (uint32_t)(arow * (SC_PAD * 2) + col * 2));
                #pragma unroll
                for (int nj = 0; nj < 2; nj++) {
                    mma16816(acc[mi][nj], ah, wbh[k16][nj], wbh[k16][2 + nj]);
                    mma16816(acc[mi][nj], ah, wbl[k16][nj], wbl[k16][2 + nj]);
                    mma16816(acc[mi][nj], al, wbh[k16][nj], wbh[k16][2 + nj]);
                }
            }
        }

        {
            float* P = HUP + (size_t)kz * BATCH * NHP + bn * 64;
            #pragma unroll
            for (int mi = 0; mi < 2; mi++) {
                int r0 = wm * 32 + mi * 16 + (lane >> 2);
                #pragma unroll
                for (int nj = 0; nj < 2; nj++) {
                    int c0 = wn * 16 + nj * 8 + (lane & 3) * 2;
                    *(float2*)(P + (size_t)r0 * NHP + c0) =
                        make_float2(acc[mi][nj][0], acc[mi][nj][1]);
                    *(float2*)(P + (size_t)(r0 + 8) * NHP + c0) =
                        make_float2(acc[mi][nj][2], acc[mi][nj][3]);
                }
            }
        }

        barid++; grid_bar(barid * NBLK);

        // combine (vectorized) + single-site hi/lo split for next step's staging
        if (tid < 256) {
            const int i = blockIdx.x * 1024 + tid * 4;
            const float* Et = scanE + (size_t)t * BATCH * NHP;
            float4 hu4 = ldcg4(HUP + i);
            #pragma unroll
            for (int z = 1; z < SC_KS; z++) {
                float4 v = ldcg4(HUP + (size_t)z * BATCH * NHP + i);
                hu4.x += v.x; hu4.y += v.y; hu4.z += v.z; hu4.w += v.w;
            }
            float4 et = *(const float4*)(Et + i);
            int ccol = i % NHP;
            float hv[4] = {hu4.x, hu4.y, hu4.z, hu4.w};
            float ev[4] = {et.x, et.y, et.z, et.w};
            float ro4[4], hu4o[4];
            __nv_bfloat16 h4[4], l4[4];
            #pragma unroll
            for (int e = 0; e < 4; e++) {
                int c = ccol + e;
                if (c < NHID) {
                    float hu = hv[e] + b_hh[c];
                    ro4[e] = tanh_fast(ev[e] + hu);
                    hu4o[e] = hu;
                } else {
                    ro4[e] = 0.f; hu4o[e] = 0.f;
                }
                h4[e] = __float2bfloat16(ro4[e]);
                l4[e] = __float2bfloat16(ro4[e] - __bfloat162float(h4[e]));
            }
            size_t o1 = (size_t)(t + 1) * BATCH * NHP + i;
            *(float4*)(RO + o1) = make_float4(ro4[0], ro4[1], ro4[2], ro4[3]);
            *(uint2*)(ROh + o1) = *(uint2*)&h4[0];
            *(uint2*)(ROl + o1) = *(uint2*)&l4[0];
            *(float4*)(HU + (size_t)t * BATCH * NHP + i) =
                make_float4(hu4o[0], hu4o[1], hu4o[2], hu4o[3]);
        }

        if (t + 1 < SLEN) { barid++; grid_bar(barid * NBLK); }
    }
}

// ---------------- fused negatives + positives ----------------
__global__ __launch_bounds__(128) void k_negpos(const int* __restrict__ samples,
                                                const int* __restrict__ data,
                                                const float* __restrict__ bias) {
    int j = blockIdx.x;
    __shared__ float fl[NHID], hus[NHID];
    __shared__ float red[4];
    const float* flat = RO + (size_t)j * NHP;
    const float* nxt  = RO + (size_t)(j + BATCH) * NHP;
    const float* huj  = HU + (size_t)j * NHP;
    int tid = threadIdx.x;

    float pp = 0.f;
    for (int c = tid; c < NHID; c += 128) {
        float f = flat[c];
        float d = f - nxt[c];
        pp += d * d;
        fl[c] = f; hus[c] = huj[c];
    }
    #pragma unroll
    for (int o = 16; o > 0; o >>= 1) pp += __shfl_down_sync(0xffffffffu, pp, o);
    if ((tid & 31) == 0) red[tid >> 5] = pp;
    __syncthreads();
    float possum = red[0] + red[1] + red[2] + red[3];
    __syncthreads();

    float s = 0.f;
    for (int n = 0; n < NS; n++) {
        int tok = samples[n * SB + j];
        const __nv_bfloat16* er = EglH + (size_t)tok * NHP;
        float part = 0.f;
        for (int c = tid; c < NHID; c += 128) {
            float v = tanh_fast(__bfloat162float(er[c]) + hus[c]);
            float d = fl[c] - v;
            part += d * d;
        }
        #pragma unroll
        for (int o = 16; o > 0; o >>= 1) part += __shfl_down_sync(0xffffffffu, part, o);
        if ((tid & 31) == 0) red[tid >> 5] = part;
        __syncthreads();
        if (tid == 0) {
            float dist = red[0] + red[1] + red[2] + red[3] - bias[tok];
            s += __expf(-TEMP * dist);
        }
        __syncthreads();
    }
    if (tid == 0) {
        float pos = TEMP * (possum - bias[data[j]]);
        float se = __expf(-pos) + s;
        atomicAdd(&ACCpos, (double)pos);
        atomicAdd(&ACClog, (double)logf(se + EPSV));
    }
}

__global__ void k_bias2(const float* __restrict__ bias) {
    __shared__ float sh[256];
    int i = blockIdx.x * blockDim.x + threadIdx.x;
    float v = 0.f;
    if (i < NTOKEN) { float b = bias[i]; v = b * b; }
    sh[threadIdx.x] = v;
    __syncthreads();
    for (int o = 128; o > 0; o >>= 1) {
        if (threadIdx.x < o) sh[threadIdx.x] += sh[threadIdx.x + o];
        __syncthreads();
    }
    if (threadIdx.x == 0) atomicAdd(&ACCbias, (double)sh[0]);
}

// fused: loss scalar + new_hidden copy in one launch
__global__ void k_out(float* out, int out_size) {
    int i = blockIdx.x * blockDim.x + threadIdx.x;
    if (i == 0 && out_size >= 1) {
        double loss = ACCpos / (double)SB + ACClog / (double)SB + ACCbias;
        out[0] = (float)loss;
    }
    if (i < BATCH * NHID && 1 + i < out_size) {
        int b = i / NHID, c = i % NHID;
        out[1 + i] = RO[(size_t)(SLEN * BATCH + b) * NHP + c];
    }
}

// ---------------- launch ----------------
extern "C" void kernel_launch(void* const* d_in, const int* in_sizes, int n_in,
                              void* d_out, int out_size) {
    const int*   data    = (const int*)d_in[0];
    const float* hidden  = (const float*)d_in[1];
    const int*   samples = (const int*)d_in[2];
    const float* emb_W   = (const float*)d_in[3];
    const float* W_ih    = (const float*)d_in[4];
    const float* b_ih    = (const float*)d_in[5];
    const float* W_hh    = (const float*)d_in[6];
    const float* b_hh    = (const float*)d_in[7];
    const float* bias    = (const float*)d_in[8];
    float* out = (float*)d_out;
    (void)in_sizes; (void)n_in;

    cudaFuncSetAttribute(k_scan, cudaFuncAttributeMaxDynamicSharedMemorySize, SMEM_SCAN);
    cudaFuncSetAttribute(k_scane_mma, cudaFuncAttributeMaxDynamicSharedMemorySize, SMEM_SE);

    k_init<<<256, 256>>>(hidden);
    k_conv<<<4096, 256>>>(emb_W, W_ih);

    dim3 ge(9, 260);
    k_egemm_mma<<<ge, 256>>>(b_ih);

    dim3 gs(9, 70);
    k_scane_mma<<<gs, 256, SMEM_SE>>>(emb_W, data, b_ih);

    k_scan<<<NBLK, 512, SMEM_SCAN>>>(W_hh, b_hh);

    k_negpos<<<SB, 128>>>(samples, data, bias);
    k_bias2<<<(NTOKEN + 255) / 256, 256>>>(bias);
    const int nb = (BATCH * NHID + 255) / 256;
    k_out<<<nb, 256>>>(out, out_size);
}

// round 14
// speedup vs baseline: 1.4671x; 1.4207x over previous
#include <cuda_runtime.h>
#include <cuda_bf16.h>
#include <cstdint>

#define NTOKEN 33278
#define NINP   400
#define KPAD   448
#define NHID   1150
#define NHP    1152
#define SLEN   70
#define BATCH  128
#define NS     10
#define SB     (SLEN*BATCH)
#define TEMP   65.0f
#define EPSV   1e-6f

// persistent scan config: 18 n-tiles(64) x 8 k-splits(144)
#define NBLK   144
#define SC_KS  8
#define SC_KC  144
#define SC_PAD 152

// ---------------- device scratch ----------------
__device__ __align__(16) __nv_bfloat16 A448[(size_t)NTOKEN * KPAD];
__device__ __align__(16) __nv_bfloat16 Wb448[(size_t)NHP * KPAD];     // W_ih hi
__device__ __align__(16) __nv_bfloat16 WbLo448[(size_t)NHP * KPAD];   // W_ih lo
__device__ __align__(16) __nv_bfloat16 EglH[(size_t)NTOKEN * NHP];
__device__ __align__(16) float scanE[(size_t)SB * NHP];
__device__ __align__(16) float RO[(size_t)(SLEN + 1) * BATCH * NHP];
__device__ __align__(16) __nv_bfloat16 ROh[(size_t)(SLEN + 1) * BATCH * NHP];
__device__ __align__(16) __nv_bfloat16 ROl[(size_t)(SLEN + 1) * BATCH * NHP];
__device__ __align__(16) float HU[(size_t)SLEN * BATCH * NHP];
__device__ __align__(16) float HUP[(size_t)SC_KS * BATCH * NHP];
__device__ double ACCpos, ACClog, ACCbias;
__device__ unsigned GBAR;

// ---------------- misc helpers ----------------
__device__ __forceinline__ float tanh_fast(float x) {
    float r; asm("tanh.approx.f32 %0, %1;" : "=f"(r) : "f"(x)); return r;
}
__device__ __forceinline__ float4 ldcg4(const float* p) {
    float4 v;
    asm volatile("ld.global.cg.v4.f32 {%0,%1,%2,%3}, [%4];"
                 : "=f"(v.x), "=f"(v.y), "=f"(v.z), "=f"(v.w) : "l"(p));
    return v;
}
__device__ __forceinline__ uint32_t smem_u32(const void* p) {
    uint32_t a;
    asm("{ .reg .u64 t; cvta.to.shared.u64 t, %1; cvt.u32.u64 %0, t; }" : "=r"(a) : "l"(p));
    return a;
}
#define SW128(o)   ((o) ^ (((o) >> 3) & 0x70))

// ---------------- HMMA helpers ----------------
__device__ __forceinline__ void ldsm4(uint32_t* r, uint32_t addr) {
    asm volatile("ldmatrix.sync.aligned.m8n8.x4.shared.b16 {%0,%1,%2,%3}, [%4];"
                 : "=r"(r[0]), "=r"(r[1]), "=r"(r[2]), "=r"(r[3]) : "r"(addr));
}
__device__ __forceinline__ void mma16816(float* d, const uint32_t* a, uint32_t b0, uint32_t b1) {
    asm volatile(
        "mma.sync.aligned.m16n8k16.row.col.f32.bf16.bf16.f32 "
        "{%0,%1,%2,%3}, {%4,%5,%6,%7}, {%8,%9}, {%0,%1,%2,%3};"
        : "+f"(d[0]), "+f"(d[1]), "+f"(d[2]), "+f"(d[3])
        : "r"(a[0]), "r"(a[1]), "r"(a[2]), "r"(a[3]), "r"(b0), "r"(b1));
}

// ---------------- grid barrier (R11-proven form) ----------------
__device__ __forceinline__ void grid_bar(unsigned target) {
    __syncthreads();
    if (threadIdx.x == 0) {
        __threadfence();
        atomicAdd(&GBAR, 1u);
        unsigned v;
        do {
            asm volatile("ld.acquire.gpu.global.u32 %0, [%1];" : "=r"(v) : "l"(&GBAR) : "memory");
        } while (v < target);
    }
    __syncthreads();
}

// ---------------- init ----------------
__global__ void k_init(const float* __restrict__ hidden) {
    int i = blockIdx.x * blockDim.x + threadIdx.x;
    int stride = gridDim.x * blockDim.x;
    if (i == 0) { ACCpos = 0.0; ACClog = 0.0; ACCbias = 0.0; GBAR = 0u; }
    const int nrow0 = BATCH * NHP;
    for (int idx = i; idx < nrow0; idx += stride) {
        int b = idx / NHP, c = idx % NHP;
        float v = (c < NHID) ? hidden[b * NHID + c] : 0.f;
        RO[idx] = v;
        __nv_bfloat16 hi = __float2bfloat16(v);
        ROh[idx] = hi;
        ROl[idx] = __float2bfloat16(v - __bfloat162float(hi));
    }
}

// ---------------- bf16 conversion / padding, vectorized (bit-identical values) ----------------
// chunks of 8 elements: NINP=400=50*8, KPAD=448=56*8 -> chunks 0..49 valid, 50..55 zero.
__global__ void k_conv(const float* __restrict__ emb_W, const float* __restrict__ W_ih) {
    size_t i = (size_t)blockIdx.x * blockDim.x + threadIdx.x;
    size_t stride = (size_t)gridDim.x * blockDim.x;
    const size_t nca = (size_t)NTOKEN * 56;     // A chunks
    const size_t ncb = (size_t)NHP * 56;        // W chunks
    for (size_t idx = i; idx < nca + ncb; idx += stride) {
        if (idx < nca) {
            size_t m = idx / 56;
            int ch = (int)(idx % 56);
            __nv_bfloat16 h[8];
            if (ch < 50) {
                const float* src = emb_W + m * NINP + ch * 8;
                float4 v0 = *(const float4*)src;
                float4 v1 = *(const float4*)(src + 4);
                float vs[8] = {v0.x, v0.y, v0.z, v0.w, v1.x, v1.y, v1.z, v1.w};
                #pragma unroll
                for (int e = 0; e < 8; e++) h[e] = __float2bfloat16(vs[e]);
            } else {
                #pragma unroll
                for (int e = 0; e < 8; e++) h[e] = __float2bfloat16(0.f);
            }
            *(uint4*)(A448 + m * KPAD + ch * 8) = *(uint4*)&h[0];
        } else {
            size_t j = idx - nca;
            size_t n = j / 56;
            int ch = (int)(j % 56);
            __nv_bfloat16 h[8], l[8];
            if (ch < 50 && n < NHID) {
                const float* src = W_ih + n * NINP + ch * 8;
                float4 v0 = *(const float4*)src;
                float4 v1 = *(const float4*)(src + 4);
                float vs[8] = {v0.x, v0.y, v0.z, v0.w, v1.x, v1.y, v1.z, v1.w};
                #pragma unroll
                for (int e = 0; e < 8; e++) {
                    h[e] = __float2bfloat16(vs[e]);
                    l[e] = __float2bfloat16(vs[e] - __bfloat162float(h[e]));
                }
            } else {
                #pragma unroll
                for (int e = 0; e < 8; e++) { h[e] = __float2bfloat16(0.f); l[e] = h[e]; }
            }
            *(uint4*)(Wb448 + n * KPAD + ch * 8) = *(uint4*)&h[0];
            *(uint4*)(WbLo448 + n * KPAD + ch * 8) = *(uint4*)&l[0];
        }
    }
}

// ---------------- vocab E GEMM via HMMA (bf16, negpos only) ----------------
__global__ __launch_bounds__(256) void k_egemm_mma(const float* __restrict__ bih) {
    __shared__ __align__(16) uint8_t smA[128 * 128];
    __shared__ __align__(16) uint8_t smB[128 * 128];
    __shared__ float bihs[128];

    const int tid = threadIdx.x, wid = tid >> 5, lane = tid & 31;
    const int bm = blockIdx.y * 128, bn = blockIdx.x * 128;
    const int wm = wid & 1, wn = wid >> 1;

    if (tid < 128) { int n = bn + tid; bihs[tid] = (n < NHID) ? bih[n] : 0.f; }

    const uint32_t sA = smem_u32(smA);
    const uint32_t sB = smem_u32(smB);

    float acc[4][4][4];
    #pragma unroll
    for (int mi = 0; mi < 4; mi++)
        #pragma unroll
        for (int nj = 0; nj < 4; nj++)
            #pragma unroll
            for (int f = 0; f < 4; f++) acc[mi][nj][f] = 0.f;

    const int grp = lane >> 3, lr = lane & 7;

    for (int ch = 0; ch < 7; ch++) {
        __syncthreads();
        #pragma unroll
        for (int i = 0; i < 4; i++) {
            int u = tid + i * 256;
            int row = u >> 3, c8 = u & 7;
            int m = bm + row; if (m >= NTOKEN) m = NTOKEN - 1;
            uint32_t swo = SW128((uint32_t)(row * 128 + c8 * 16));
            *(uint4*)(smA + swo) = *(const uint4*)(A448 + (size_t)m * KPAD + ch * 64 + c8 * 8);
            *(uint4*)(smB + swo) = *(const uint4*)(Wb448 + (size_t)(bn + row) * KPAD + ch * 64 + c8 * 8);
        }
        __syncthreads();

        #pragma unroll
        for (int k16 = 0; k16 < 4; k16++) {
            const int k0 = k16 * 16;
            uint32_t bfr[2][4];
            #pragma unroll
            for (int j = 0; j < 2; j++) {
                int row = wn * 32 + j * 16 + (grp & 1) * 8 + lr;
                int col = k0 + (grp >> 1) * 8;
                ldsm4(bfr[j], sB + SW128((uint32_t)(row * 128 + col * 2)));
            }
            #pragma unroll
            for (int mi = 0; mi < 4; mi++) {
                uint32_t afr[4];
                int row = wm * 64 + mi * 16 + (grp & 1) * 8 + lr;
                int col = k0 + (grp >> 1) * 8;
                ldsm4(afr, sA + SW128((uint32_t)(row * 128 + col * 2)));
                #pragma unroll
                for (int nj = 0; nj < 4; nj++) {
                    const uint32_t* bf = bfr[nj >> 1];
                    mma16816(acc[mi][nj], afr, bf[nj & 1], bf[2 + (nj & 1)]);
                }
            }
        }
    }

    #pragma unroll
    for (int mi = 0; mi < 4; mi++) {
        int row0 = wm * 64 + mi * 16 + (lane >> 2);
        int m0g = bm + row0, m1g = m0g + 8;
        #pragma unroll
        for (int nj = 0; nj < 4; nj++) {
            int cloc = wn * 32 + nj * 8 + (lane & 3) * 2;
            float b0 = bihs[cloc], b1 = bihs[cloc + 1];
            int n = bn + cloc;
            if (m0g < NTOKEN) {
                __nv_bfloat162 p = __floats2bfloat162_rn(acc[mi][nj][0] + b0, acc[mi][nj][1] + b1);
                *(__nv_bfloat162*)(EglH + (size_t)m0g * NHP + n) = p;
            }
            if (m1g < NTOKEN) {
                __nv_bfloat162 p = __floats2bfloat162_rn(acc[mi][nj][2] + b0, acc[mi][nj][3] + b1);
                *(__nv_bfloat162*)(EglH + (size_t)m1g * NHP + n) = p;
            }
        }
    }
}

// ---------------- scanE via split-bf16 HMMA (gathered rows, fp32-grade) ----------------
#define SMEM_SE (4 * 16384 + 512)
__global__ __launch_bounds__(256) void k_scane_mma(const float* __restrict__ A,
                                                   const int* __restrict__ data,
                                                   const float* __restrict__ bih) {
    extern __shared__ char sm[];
    uint8_t* smAh = (uint8_t*)sm;
    uint8_t* smAl = smAh + 16384;
    uint8_t* smBh = smAl + 16384;
    uint8_t* smBl = smBh + 16384;
    float* bihs = (float*)(smBl + 16384);

    const int tid = threadIdx.x, wid = tid >> 5, lane = tid & 31;
    const int bm = blockIdx.y * 128, bn = blockIdx.x * 128;
    const int wm = wid & 1, wn = wid >> 1;
    const int grp = lane >> 3, lr = lane & 7;

    if (tid < 128) { int n = bn + tid; bihs[tid] = (n < NHID) ? bih[n] : 0.f; }

    const uint32_t sAh = smem_u32(smAh), sAl = smem_u32(smAl);
    const uint32_t sBh = smem_u32(smBh), sBl = smem_u32(smBl);

    const int arow = tid >> 1, ahalf = tid & 1;
    const int tok = data[bm + arow];
    const float* Arow = A + (size_t)tok * NINP;

    float acc[4][4][4];
    #pragma unroll
    for (int mi = 0; mi < 4; mi++)
        #pragma unroll
        for (int nj = 0; nj < 4; nj++)
            #pragma unroll
            for (int f = 0; f < 4; f++) acc[mi][nj][f] = 0.f;

    for (int ch = 0; ch < 7; ch++) {
        __syncthreads();
        #pragma unroll
        for (int s = 0; s < 4; s++) {
            int lc = ahalf * 32 + s * 8;
            int gc = ch * 64 + lc;
            __nv_bfloat16 h[8], l[8];
            if (gc + 8 <= NINP) {
                float4 v0 = *(const float4*)(Arow + gc);
                float4 v1 = *(const float4*)(Arow + gc + 4);
                float vs[8] = {v0.x, v0.y, v0.z, v0.w, v1.x, v1.y, v1.z, v1.w};
                #pragma unroll
                for (int e = 0; e < 8; e++) {
                    h[e] = __float2bfloat16(vs[e]);
                    l[e] = __float2bfloat16(vs[e] - __bfloat162float(h[e]));
                }
            } else {
                #pragma unroll
                for (int e = 0; e < 8; e++) { h[e] = __float2bfloat16(0.f); l[e] = h[e]; }
            }
            uint32_t swo = SW128((uint32_t)(arow * 128 + lc * 2));
            *(uint4*)(smAh + swo) = *(uint4*)&h[0];
            *(uint4*)(smAl + swo) = *(uint4*)&l[0];
        }
        #pragma unroll
        for (int i = 0; i < 4; i++) {
            int u = tid + i * 256;
            int row = u >> 3, c8 = u & 7;
            uint32_t swo = SW128((uint32_t)(row * 128 + c8 * 16));
            size_t go = (size_t)(bn + row) * KPAD + ch * 64 + c8 * 8;
            *(uint4*)(smBh + swo) = *(const uint4*)(Wb448 + go);
            *(uint4*)(smBl + swo) = *(const uint4*)(WbLo448 + go);
        }
        __syncthreads();

        #pragma unroll
        for (int k16 = 0; k16 < 4; k16++) {
            const int col = k16 * 16 + (grp >> 1) * 8;
            uint32_t bh[2][4], bl[2][4];
            #pragma unroll
            for (int j = 0; j < 2; j++) {
                int row = wn * 32 + j * 16 + (grp & 1) * 8 + lr;
                uint32_t off = SW128((uint32_t)(row * 128 + col * 2));
                ldsm4(bh[j], sBh + off);
                ldsm4(bl[j], sBl + off);
            }
            #pragma unroll
            for (int mi = 0; mi < 4; mi++) {
                int row = wm * 64 + mi * 16 + (grp & 1) * 8 + lr;
                uint32_t off = SW128((uint32_t)(row * 128 + col * 2));
                uint32_t ah[4], al[4];
                ldsm4(ah, sAh + off);
                ldsm4(al, sAl + off);
                #pragma unroll
                for (int nj = 0; nj < 4; nj++) {
                    const uint32_t* bfh = bh[nj >> 1];
                    const uint32_t* bfl = bl[nj >> 1];
                    mma16816(acc[mi][nj], ah, bfh[nj & 1], bfh[2 + (nj & 1)]);
                    mma16816(acc[mi][nj], ah, bfl[nj & 1], bfl[2 + (nj & 1)]);
                    mma16816(acc[mi][nj], al, bfh[nj & 1], bfh[2 + (nj & 1)]);
                }
            }
        }
    }

    #pragma unroll
    for (int mi = 0; mi < 4; mi++) {
        int row0 = wm * 64 + mi * 16 + (lane >> 2);
        int j0 = bm + row0, j1 = j0 + 8;
        #pragma unroll
        for (int nj = 0; nj < 4; nj++) {
            int cloc = wn * 32 + nj * 8 + (lane & 3) * 2;
            float b0 = bihs[cloc], b1 = bihs[cloc + 1];
            int n = bn + cloc;
            *(float2*)(scanE + (size_t)j0 * NHP + n) =
                make_float2(acc[mi][nj][0] + b0, acc[mi][nj][1] + b1);
            *(float2*)(scanE + (size_t)j1 * NHP + n) =
                make_float2(acc[mi][nj][2] + b0, acc[mi][nj][3] + b1);
        }
    }
}

// ---------------- persistent scan: bf16-split HMMA, W fragments in registers ----------------
#define SMEM_SCAN (2 * 128 * SC_PAD * 2 + 2 * 64 * SC_PAD * 2)

__global__ __launch_bounds__(512) void k_scan(const float* __restrict__ W_hh,
                                              const float* __restrict__ b_hh) {
    extern __shared__ char smc[];
    __nv_bfloat16* Ahi = (__nv_bfloat16*)smc;
    __nv_bfloat16* Alo = Ahi + 128 * SC_PAD;
    __nv_bfloat16* Whi = Alo + 128 * SC_PAD;
    __nv_bfloat16* Wlo = Whi + 64 * SC_PAD;
    const uint32_t sAhi = smem_u32(Ahi), sAlo = smem_u32(Alo);
    const uint32_t sWhi = smem_u32(Whi), sWlo = smem_u32(Wlo);

    const int tid = threadIdx.x, wid = tid >> 5, lane = tid & 31;
    const int bn = blockIdx.x / SC_KS;
    const int kz = blockIdx.x % SC_KS;
    const int kbase = kz * SC_KC;
    const int wm = wid & 3, wn = wid >> 2;
    const int grp = lane >> 3, lr = lane & 7;

    for (int idx = tid; idx < 64 * SC_KC; idx += 512) {
        int n = idx / SC_KC, k = idx % SC_KC;
        int gn = bn * 64 + n, gk = kbase + k;
        float w = (gn < NHID && gk < NHID) ? W_hh[(size_t)gn * NHID + gk] : 0.f;
        __nv_bfloat16 hi = __float2bfloat16(w);
        float lo = w - __bfloat162float(hi);
        Whi[n * SC_PAD + k] = hi;
        Wlo[n * SC_PAD + k] = __float2bfloat16(lo);
    }
    __syncthreads();

    // hoist loop-invariant W fragments into registers (once for all 70 steps)
    uint32_t wbh[9][4], wbl[9][4];
    {
        const int brow = wn * 16 + (grp & 1) * 8 + lr;
        #pragma unroll
        for (int k16 = 0; k16 < 9; k16++) {
            const int col = k16 * 16 + (grp >> 1) * 8;
            ldsm4(wbh[k16], sWhi + (uint32_t)(brow * (SC_PAD * 2) + col * 2));
            ldsm4(wbl[k16], sWlo + (uint32_t)(brow * (SC_PAD * 2) + col * 2));
        }
    }

    unsigned barid = 0;

    for (int t = 0; t < SLEN; t++) {
        // stage A: straight copy of pre-split ROh/ROl
        {
            const __nv_bfloat16* Sh = ROh + (size_t)t * BATCH * NHP + kbase;
            const __nv_bfloat16* Sl = ROl + (size_t)t * BATCH * NHP + kbase;
            #pragma unroll
            for (int it = 0; it < 5; it++) {
                int idx = tid + it * 512;
                if (idx < 2304) {                 // 128 rows x 18 uint4-chunks
                    int row = idx / 18, ch = idx % 18;
                    size_t gso = (size_t)row * NHP + ch * 8;
                    int dso = row * SC_PAD + ch * 8;
                    *(uint4*)(Ahi + dso) = *(const uint4*)(Sh + gso);
                    *(uint4*)(Alo + dso) = *(const uint4*)(Sl + gso);
                }
            }
        }
        __syncthreads();

        float acc[2][2][4];
        #pragma unroll
        for (int mi = 0; mi < 2; mi++)
            #pragma unroll
            for (int nj = 0; nj < 2; nj++)
                #pragma unroll
                for (int f = 0; f < 4; f++) acc[mi][nj][f] = 0.f;

        #pragma unroll
        for (int k16 = 0; k16 < 9; k16++) {
            const int col = k16 * 16 + (grp >> 1) * 8;
            #pragma unroll
            for (int mi = 0; mi < 2; mi++) {
                const int arow = wm * 32 + mi * 16 + (grp & 1) * 8 + lr;
                uint32_t ah[4], al[4];
                ldsm4(ah, sAhi + (uint32_t)(arow * (SC_PAD * 2) + col * 2));
                ldsm4(al, sAlo + (uint32_t)(arow * (SC_PAD * 2) + col * 2));
                #pragma unroll
                for (int nj = 0; nj < 2; nj++) {
                    mma16816(acc[mi][nj], ah, wbh[k16][nj], wbh[k16][2 + nj]);
                    mma16816(acc[mi][nj], ah, wbl[k16][nj], wbl[k16][2 + nj]);
                    mma16816(acc[mi][nj], al, wbh[k16][nj], wbh[k16][2 + nj]);
                }
            }
        }

        {
            float* P = HUP + (size_t)kz * BATCH * NHP + bn * 64;
            #pragma unroll
            for (int mi = 0; mi < 2; mi++) {
                int r0 = wm * 32 + mi * 16 + (lane >> 2);
                #pragma unroll
                for (int nj = 0; nj < 2; nj++) {
                    int c0 = wn * 16 + nj * 8 + (lane & 3) * 2;
                    *(float2*)(P + (size_t)r0 * NHP + c0) =
                        make_float2(acc[mi][nj][0], acc[mi][nj][1]);
                    *(float2*)(P + (size_t)(r0 + 8) * NHP + c0) =
                        make_float2(acc[mi][nj][2], acc[mi][nj][3]);
                }
            }
        }

        barid++; grid_bar(barid * NBLK);

        // combine (vectorized) + single-site hi/lo split for next step's staging
        if (tid < 256) {
            const int i = blockIdx.x * 1024 + tid * 4;
            const float* Et = scanE + (size_t)t * BATCH * NHP;
            float4 hu4 = ldcg4(HUP + i);
            #pragma unroll
            for (int z = 1; z < SC_KS; z++) {
                float4 v = ldcg4(HUP + (size_t)z * BATCH * NHP + i);
                hu4.x += v.x; hu4.y += v.y; hu4.z += v.z; hu4.w += v.w;
            }
            float4 et = *(const float4*)(Et + i);
            int ccol = i % NHP;
            float hv[4] = {hu4.x, hu4.y, hu4.z, hu4.w};
            float ev[4] = {et.x, et.y, et.z, et.w};
            float ro4[4], hu4o[4];
            __nv_bfloat16 h4[4], l4[4];
            #pragma unroll
            for (int e = 0; e < 4; e++) {
                int c = ccol + e;
                if (c < NHID) {
                    float hu = hv[e] + b_hh[c];
                    ro4[e] = tanh_fast(ev[e] + hu);
                    hu4o[e] = hu;
                } else {
                    ro4[e] = 0.f; hu4o[e] = 0.f;
                }
                h4[e] = __float2bfloat16(ro4[e]);
                l4[e] = __float2bfloat16(ro4[e] - __bfloat162float(h4[e]));
            }
            size_t o1 = (size_t)(t + 1) * BATCH * NHP + i;
            *(float4*)(RO + o1) = make_float4(ro4[0], ro4[1], ro4[2], ro4[3]);
            *(uint2*)(ROh + o1) = *(uint2*)&h4[0];
            *(uint2*)(ROl + o1) = *(uint2*)&l4[0];
            *(float4*)(HU + (size_t)t * BATCH * NHP + i) =
                make_float4(hu4o[0], hu4o[1], hu4o[2], hu4o[3]);
        }

        if (t + 1 < SLEN) { barid++; grid_bar(barid * NBLK); }
    }
}

// ---------------- fused negatives + positives ----------------
__global__ __launch_bounds__(128) void k_negpos(const int* __restrict__ samples,
                                                const int* __restrict__ data,
                                                const float* __restrict__ bias) {
    int j = blockIdx.x;
    __shared__ float fl[NHID], hus[NHID];
    __shared__ float red[4];
    const float* flat = RO + (size_t)j * NHP;
    const float* nxt  = RO + (size_t)(j + BATCH) * NHP;
    const float* huj  = HU + (size_t)j * NHP;
    int tid = threadIdx.x;

    float pp = 0.f;
    for (int c = tid; c < NHID; c += 128) {
        float f = flat[c];
        float d = f - nxt[c];
        pp += d * d;
        fl[c] = f; hus[c] = huj[c];
    }
    #pragma unroll
    for (int o = 16; o > 0; o >>= 1) pp += __shfl_down_sync(0xffffffffu, pp, o);
    if ((tid & 31) == 0) red[tid >> 5] = pp;
    __syncthreads();
    float possum = red[0] + red[1] + red[2] + red[3];
    __syncthreads();

    float s = 0.f;
    for (int n = 0; n < NS; n++) {
        int tok = samples[n * SB + j];
        const __nv_bfloat16* er = EglH + (size_t)tok * NHP;
        float part = 0.f;
        for (int c = tid; c < NHID; c += 128) {
            float v = tanh_fast(__bfloat162float(er[c]) + hus[c]);
            float d = fl[c] - v;
            part += d * d;
        }
        #pragma unroll
        for (int o = 16; o > 0; o >>= 1) part += __shfl_down_sync(0xffffffffu, part, o);
        if ((tid & 31) == 0) red[tid >> 5] = part;
        __syncthreads();
        if (tid == 0) {
            float dist = red[0] + red[1] + red[2] + red[3] - bias[tok];
            s += __expf(-TEMP * dist);
        }
        __syncthreads();
    }
    if (tid == 0) {
        float pos = TEMP * (possum - bias[data[j]]);
        float se = __expf(-pos) + s;
        atomicAdd(&ACCpos, (double)pos);
        atomicAdd(&ACClog, (double)logf(se + EPSV));
    }
}

__global__ void k_bias2(const float* __restrict__ bias) {
    __shared__ float sh[256];
    int i = blockIdx.x * blockDim.x + threadIdx.x;
    float v = 0.f;
    if (i < NTOKEN) { float b = bias[i]; v = b * b; }
    sh[threadIdx.x] = v;
    __syncthreads();
    for (int o = 128; o > 0; o >>= 1) {
        if (threadIdx.x < o) sh[threadIdx.x] += sh[threadIdx.x + o];
        __syncthreads();
    }
    if (threadIdx.x == 0) atomicAdd(&ACCbias, (double)sh[0]);
}

// fused: loss scalar + new_hidden copy in one launch
__global__ void k_out(float* out, int out_size) {
    int i = blockIdx.x * blockDim.x + threadIdx.x;
    if (i == 0 && out_size >= 1) {
        double loss = ACCpos / (double)SB + ACClog / (double)SB + ACCbias;
        out[0] = (float)loss;
    }
    if (i < BATCH * NHID && 1 + i < out_size) {
        int b = i / NHID, c = i % NHID;
        out[1 + i] = RO[(size_t)(SLEN * BATCH + b) * NHP + c];
    }
}

// ---------------- launch ----------------
extern "C" void kernel_launch(void* const* d_in, const int* in_sizes, int n_in,
                              void* d_out, int out_size) {
    const int*   data    = (const int*)d_in[0];
    const float* hidden  = (const float*)d_in[1];
    const int*   samples = (const int*)d_in[2];
    const float* emb_W   = (const float*)d_in[3];
    const float* W_ih    = (const float*)d_in[4];
    const float* b_ih    = (const float*)d_in[5];
    const float* W_hh    = (const float*)d_in[6];
    const float* b_hh    = (const float*)d_in[7];
    const float* bias    = (const float*)d_in[8];
    float* out = (float*)d_out;
    (void)in_sizes; (void)n_in;

    cudaFuncSetAttribute(k_scan, cudaFuncAttributeMaxDynamicSharedMemorySize, SMEM_SCAN);
    cudaFuncSetAttribute(k_scane_mma, cudaFuncAttributeMaxDynamicSharedMemorySize, SMEM_SE);

    k_init<<<256, 256>>>(hidden);
    k_conv<<<4096, 256>>>(emb_W, W_ih);

    dim3 ge(9, 260);
    k_egemm_mma<<<ge, 256>>>(b_ih);

    dim3 gs(9, 70);
    k_scane_mma<<<gs, 256, SMEM_SE>>>(emb_W, data, b_ih);

    k_scan<<<NBLK, 512, SMEM_SCAN>>>(W_hh, b_hh);

    k_negpos<<<SB, 128>>>(samples, data, bias);
    k_bias2<<<(NTOKEN + 255) / 256, 256>>>(bias);
    const int nb = (BATCH * NHID + 255) / 256;
    k_out<<<nb, 256>>>(out, out_size);
}